// round 13
// baseline (speedup 1.0000x reference)
#include <cuda_runtime.h>
#include <math.h>
#include <stdint.h>

#define BATCH   4
#define SEQLEN  2048
#define DMODEL  1024
#define DINNER  2048
#define DSTATE  64
#define NHEADS  32
#define HEADDIM 64
#define CONVDIM 2176          // DINNER + 2*DSTATE
#define DIP     4256          // 2*DINNER + 2*DSTATE + NHEADS
#define MROWS   (BATCH*SEQLEN) // 8192
#define DTOFF   4224          // DINNER + CONVDIM

// ---- scratch (static device arrays; same footprint as passing builds) ----
// Alias plan (per-direction stream overlap):
//   g_xBC[1] region : tf32 x  (clobbered by conv1, after both inprojs)
//   g_xBC[0] region : tf32 W_in dir0; then conv0 data; then tf32 W_out f,b
//   g_y[1]   region : tf32 W_in dir1 (clobbered by scan1, after inproj1)
//   g_y[0]   region : free until scan0 writes it
__device__ float g_zx [2][MROWS][DIP];
__device__ float g_xBC[2][MROWS][CONVDIM];
__device__ float g_dt [2][NHEADS][MROWS];   // softplus(dt) TRANSPOSED (h-major)
__device__ float g_y  [2][MROWS][DINNER];

__device__ __forceinline__ int fliprow(int m, int flip) {
    return flip ? ((m & ~(SEQLEN - 1)) | ((SEQLEN - 1) - (m & (SEQLEN - 1)))) : m;
}

__device__ __forceinline__ uint32_t f2tf32(float x) {
    uint32_t u;
    asm("cvt.rna.tf32.f32 %0, %1;" : "=r"(u) : "f"(x));
    return u;
}

// ---- packed f32x2 helpers (Blackwell) ----
typedef unsigned long long ull;
__device__ __forceinline__ ull pack2(float lo, float hi) {
    ull r; asm("mov.b64 %0, {%1, %2};" : "=l"(r) : "f"(lo), "f"(hi)); return r;
}
#define MUL2(d, a, b)    asm("mul.rn.f32x2 %0, %1, %2;" : "=l"(d) : "l"(a), "l"(b))
#define FMA2(d, a, b, c) asm("fma.rn.f32x2 %0, %1, %2, %3;" : "=l"(d) : "l"(a), "l"(b), "l"(c))
#define FMA2ACC(d, a, b) asm("fma.rn.f32x2 %0, %1, %2, %0;" : "+l"(d) : "l"(a), "l"(b))

// ---- cp.async ----
__device__ __forceinline__ void cp_async16(void* smem_dst, const float* gmem_src, int src_bytes) {
    uint32_t s = (uint32_t)__cvta_generic_to_shared(smem_dst);
    asm volatile("cp.async.cg.shared.global [%0], [%1], 16, %2;\n"
                 :: "r"(s), "l"(gmem_src), "r"(src_bytes));
}
__device__ __forceinline__ void cp_commit() { asm volatile("cp.async.commit_group;\n"); }
__device__ __forceinline__ void cp_wait0()  { asm volatile("cp.async.wait_group 0;\n"); }
__device__ __forceinline__ void cp_wait1()  { asm volatile("cp.async.wait_group 1;\n"); }

__device__ __forceinline__ void mma_16n8k8(float c[4], const uint32_t a[4], const uint32_t b[2]) {
    asm volatile("mma.sync.aligned.m16n8k8.row.col.f32.tf32.tf32.f32 "
                 "{%0,%1,%2,%3}, {%4,%5,%6,%7}, {%8,%9}, {%0,%1,%2,%3};"
                 : "+f"(c[0]), "+f"(c[1]), "+f"(c[2]), "+f"(c[3])
                 : "r"(a[0]), "r"(a[1]), "r"(a[2]), "r"(a[3]), "r"(b[0]), "r"(b[1]));
}

// ============================================================================
// Pre-round fp32 -> tf32-precision fp32 into aliased scratch regions.
// 0: x -> g_xBC[1]   1: W_in0 -> g_xBC[0]   2: W_in1 -> g_y[1]
// 3: W_out f -> g_xBC[0]   4: W_out b -> g_xBC[0] + DMODEL*DINNER
// ============================================================================
__global__ void __launch_bounds__(256)
k_round(const float* __restrict__ src, int which, int n4)
{
    float* dst;
    switch (which) {
        case 0:  dst = &g_xBC[1][0][0]; break;
        case 1:  dst = &g_xBC[0][0][0]; break;
        case 2:  dst = &g_y[1][0][0]; break;
        case 3:  dst = &g_xBC[0][0][0]; break;
        default: dst = &g_xBC[0][0][0] + (size_t)DMODEL * DINNER; break;
    }
    const int i = blockIdx.x * blockDim.x + threadIdx.x;
    if (i < n4) {
        float4 v = ((const float4*)src)[i];
        v.x = __uint_as_float(f2tf32(v.x));
        v.y = __uint_as_float(f2tf32(v.y));
        v.z = __uint_as_float(f2tf32(v.z));
        v.w = __uint_as_float(f2tf32(v.w));
        ((float4*)dst)[i] = v;
    }
}

// ============================================================================
// tf32 GEMM — exact R7 config (best measured): BM=BN=128, BK=16, 256 thr,
// 8 warps (2x4) of 64x32 tiles, 2-stage cp.async, static smem, 2 CTAs/SM.
// ============================================================================
#define SPITCH 20

template<int N, int K>
__device__ __forceinline__ void tgemm_nt_body(
    const float* __restrict__ A, int flipA,
    const float* __restrict__ W,
    float* __restrict__ C, int accum)
{
    __shared__ float As[2][128][SPITCH];
    __shared__ float Bs[2][128][SPITCH];

    const int tid   = threadIdx.x;
    const int mBase = blockIdx.y * 128;
    const int nBase = blockIdx.x * 128;

    const int r0 = tid >> 1;              // 0..127
    const int kc = (tid & 1) * 8;         // 0 or 8

    const int am = fliprow(mBase + r0, flipA);
    const float* Ar = A + (size_t)am * K + kc;
    const int wn = nBase + r0;
    const float* Wr = W + (size_t)wn * K + kc;
    const int wb = (wn < N) ? 16 : 0;

    const int lane = tid & 31;
    const int g    = lane >> 2;
    const int tig  = lane & 3;
    const int warp = tid >> 5;
    const int wm   = (warp & 1) * 64;
    const int wnn  = (warp >> 1) * 32;

    float acc[4][4][4];
    #pragma unroll
    for (int mt = 0; mt < 4; mt++)
        #pragma unroll
        for (int nt = 0; nt < 4; nt++)
            #pragma unroll
            for (int c = 0; c < 4; c++) acc[mt][nt][c] = 0.f;

    auto issueChunk = [&](int ch) {
        const int st = ch & 1;
        const int ko = ch * 16;
        float* as = &As[st][r0][kc];
        float* bs = &Bs[st][r0][kc];
        cp_async16(as,     Ar + ko,     16);
        cp_async16(as + 4, Ar + ko + 4, 16);
        cp_async16(bs,     Wr + ko,     wb);
        cp_async16(bs + 4, Wr + ko + 4, wb);
    };

    issueChunk(0); cp_commit();

    constexpr int NT = K / 16;
    #pragma unroll 1
    for (int kt = 0; kt < NT; kt++) {
        cp_wait0();
        __syncthreads();

        if (kt + 1 < NT) { issueChunk(kt + 1); cp_commit(); }

        const int st = kt & 1;
        #pragma unroll
        for (int kk = 0; kk < 16; kk += 8) {
            uint32_t af[4][4], bf[4][2];
            #pragma unroll
            for (int mt = 0; mt < 4; mt++) {
                const int m0 = wm + mt * 16 + g;
                af[mt][0] = __float_as_uint(As[st][m0][kk + tig]);
                af[mt][1] = __float_as_uint(As[st][m0 + 8][kk + tig]);
                af[mt][2] = __float_as_uint(As[st][m0][kk + tig + 4]);
                af[mt][3] = __float_as_uint(As[st][m0 + 8][kk + tig + 4]);
            }
            #pragma unroll
            for (int nt = 0; nt < 4; nt++) {
                const int n0 = wnn + nt * 8 + g;
                bf[nt][0] = __float_as_uint(Bs[st][n0][kk + tig]);
                bf[nt][1] = __float_as_uint(Bs[st][n0][kk + tig + 4]);
            }
            #pragma unroll
            for (int mt = 0; mt < 4; mt++)
                #pragma unroll
                for (int nt = 0; nt < 4; nt++)
                    mma_16n8k8(acc[mt][nt], af[mt], bf[nt]);
        }
        __syncthreads();
    }

    #pragma unroll
    for (int mt = 0; mt < 4; mt++) {
        const int m0 = mBase + wm + mt * 16 + g;
        float* crow0 = C + (size_t)m0 * N;
        float* crow1 = C + (size_t)(m0 + 8) * N;
        #pragma unroll
        for (int nt = 0; nt < 4; nt++) {
            const int n = nBase + wnn + nt * 8 + tig * 2;
            if (n < N) {
                float2 v0 = make_float2(acc[mt][nt][0], acc[mt][nt][1]);
                float2 v1 = make_float2(acc[mt][nt][2], acc[mt][nt][3]);
                if (accum) {
                    float2 o0 = *(const float2*)(crow0 + n);
                    float2 o1 = *(const float2*)(crow1 + n);
                    v0.x += o0.x; v0.y += o0.y; v1.x += o1.x; v1.y += o1.y;
                }
                *(float2*)(crow0 + n) = v0;
                *(float2*)(crow1 + n) = v1;
            }
        }
    }
}

__global__ void __launch_bounds__(256)
k_inproj(int dir)
{
    const float* xr = &g_xBC[1][0][0];
    const float* W  = dir ? &g_y[1][0][0] : &g_xBC[0][0][0];
    tgemm_nt_body<DIP, DMODEL>(xr, dir, W, &g_zx[dir][0][0], 0);
}

__global__ void __launch_bounds__(256)
k_outproj(float* __restrict__ out, int dir, int accum)
{
    const float* W = &g_xBC[0][0][0] + (size_t)dir * DMODEL * DINNER;
    tgemm_nt_body<DMODEL, DINNER>(&g_y[dir][0][0], dir, W, out, accum);
}

// ============================================================================
// Depthwise causal conv (width 4) + bias + silu + dt softplus. Per-direction.
// ============================================================================
__global__ void __launch_bounds__(256)
k_conv(const float* __restrict__ cw, const float* __restrict__ cb,
       const float* __restrict__ dtb, int dir)
{
    const int c = blockIdx.x * blockDim.x + threadIdx.x;
    const int m = blockIdx.y;
    const int l = m & (SEQLEN - 1);

    if (c < CONVDIM) {
        float acc = cb[c];
        #pragma unroll
        for (int j = 0; j < 4; j++) {
            const int ls = l - 3 + j;
            if (ls >= 0)
                acc = fmaf(cw[c * 4 + j], g_zx[dir][m - 3 + j][DINNER + c], acc);
        }
        g_xBC[dir][m][c] = acc / (1.f + expf(-acc));
    } else if (c < CONVDIM + NHEADS) {
        const int h = c - CONVDIM;
        const float v = g_zx[dir][m][DTOFF + h] + dtb[h];
        g_dt[dir][h][m] = (v > 20.f) ? v : log1pf(expf(v));
    }
}

// ============================================================================
// SSD scan v2 (R7 structure), per-direction.
// ============================================================================
#define SCHUNK 8
__global__ void __launch_bounds__(64)
k_scan(const float* __restrict__ Al, const float* __restrict__ Dp, int dir)
{
    const int h = blockIdx.x, b = blockIdx.y;
    const int tid = threadIdx.x;
    const float Ah = -expf(Al[h]);
    const float Dh = Dp[h];
    const int mBase = b * SEQLEN;

    __shared__ __align__(16) float sX[2][SCHUNK][64];
    __shared__ __align__(16) float sB[2][SCHUNK][64];
    __shared__ __align__(16) float sC[2][SCHUNK][64];
    __shared__ __align__(16) float sDt[2][SCHUNK];

    ull S2[32];
    #pragma unroll
    for (int i = 0; i < 32; i++) S2[i] = 0ull;

    auto issue = [&](int buf, int chunk) {
        #pragma unroll
        for (int j = 0; j < 6; j++) {
            const int idx = tid + 64 * j;
            const int region = idx >> 7;
            const int r = idx & 127;
            const int t = r >> 4;
            const int o = (r & 15) * 4;
            const float* row = &g_xBC[dir][mBase + chunk * SCHUNK + t][0];
            const float* src;
            float* dst;
            if (region == 0)      { src = row + h * HEADDIM + o;     dst = &sX[buf][t][o]; }
            else if (region == 1) { src = row + DINNER + o;          dst = &sB[buf][t][o]; }
            else                  { src = row + DINNER + DSTATE + o; dst = &sC[buf][t][o]; }
            cp_async16(dst, src, 16);
        }
        if (tid < 2)
            cp_async16(&sDt[buf][tid * 4],
                       &g_dt[dir][h][mBase + chunk * SCHUNK + tid * 4], 16);
    };

    constexpr int NC = SEQLEN / SCHUNK;
    issue(0, 0);
    cp_commit();

    #pragma unroll 1
    for (int ch = 0; ch < NC; ch++) {
        const int buf = ch & 1;
        if (ch + 1 < NC) {
            issue(buf ^ 1, ch + 1);
            cp_commit();
            cp_wait1();
        } else {
            cp_wait0();
        }
        __syncthreads();

        #pragma unroll
        for (int t = 0; t < SCHUNK; t++) {
            const float dt = sDt[buf][t];
            const float dA = expf(dt * Ah);
            const float xp = sX[buf][t][tid];
            const float cf = dt * xp;
            const ull dA2 = pack2(dA, dA);
            const ull cf2 = pack2(cf, cf);

            ull y2[4] = {0ull, 0ull, 0ull, 0ull};
            #pragma unroll
            for (int q = 0; q < 16; q++) {
                const ulonglong2 bq = *(const ulonglong2*)&sB[buf][t][q * 4];
                const ulonglong2 cq = *(const ulonglong2*)&sC[buf][t][q * 4];
                ull tmp;
                MUL2(tmp, S2[2*q],   dA2); FMA2(S2[2*q],   cf2, bq.x, tmp);
                FMA2ACC(y2[(2*q)   & 3], S2[2*q],   cq.x);
                MUL2(tmp, S2[2*q+1], dA2); FMA2(S2[2*q+1], cf2, bq.y, tmp);
                FMA2ACC(y2[(2*q+1) & 3], S2[2*q+1], cq.y);
            }
            float ys = 0.f;
            #pragma unroll
            for (int a = 0; a < 4; a++) {
                uint32_t lo, hi;
                asm("mov.b64 {%0, %1}, %2;" : "=r"(lo), "=r"(hi) : "l"(y2[a]));
                ys += __uint_as_float(lo) + __uint_as_float(hi);
            }
            g_y[dir][mBase + ch * SCHUNK + t][h * HEADDIM + tid] = ys + Dh * xp;
        }
        __syncthreads();
    }
}

// ============================================================================
// Gate with silu(z), RMSNorm, norm_w scale, tf32 pre-round. Per-direction.
// ============================================================================
__global__ void __launch_bounds__(256)
k_gate(const float* __restrict__ nw, int dir)
{
    const int m = blockIdx.x;
    const int tid = threadIdx.x;

    const float4* y4p = (const float4*)&g_y[dir][m][0];
    const float4* z4p = (const float4*)&g_zx[dir][m][0];

    float4 v[2];
    float ss = 0.f;
    #pragma unroll
    for (int i = 0; i < 2; i++) {
        const int idx = tid + i * 256;
        const float4 y4 = y4p[idx];
        const float4 z4 = z4p[idx];
        float4 r;
        r.x = y4.x * (z4.x / (1.f + expf(-z4.x)));
        r.y = y4.y * (z4.y / (1.f + expf(-z4.y)));
        r.z = y4.z * (z4.z / (1.f + expf(-z4.z)));
        r.w = y4.w * (z4.w / (1.f + expf(-z4.w)));
        v[i] = r;
        ss += r.x * r.x + r.y * r.y + r.z * r.z + r.w * r.w;
    }
    __shared__ float red[8];
    #pragma unroll
    for (int o = 16; o > 0; o >>= 1) ss += __shfl_xor_sync(0xffffffffu, ss, o);
    if ((tid & 31) == 0) red[tid >> 5] = ss;
    __syncthreads();
    if (tid < 8) {
        float t = red[tid];
        #pragma unroll
        for (int o = 4; o > 0; o >>= 1) t += __shfl_xor_sync(0xffu, t, o);
        if (tid == 0) red[0] = t;
    }
    __syncthreads();
    const float scale = rsqrtf(red[0] / (float)DINNER + 1e-5f);

    float4* o4p = (float4*)&g_y[dir][m][0];
    #pragma unroll
    for (int i = 0; i < 2; i++) {
        const int idx = tid + i * 256;
        const float4 w4 = ((const float4*)nw)[idx];
        float4 r = v[i];
        r.x = __uint_as_float(f2tf32(r.x * scale * w4.x));
        r.y = __uint_as_float(f2tf32(r.y * scale * w4.y));
        r.z = __uint_as_float(f2tf32(r.z * scale * w4.z));
        r.w = __uint_as_float(f2tf32(r.w * scale * w4.w));
        o4p[idx] = r;
    }
}

// ============================================================================
extern "C" void kernel_launch(void* const* d_in, const int* in_sizes, int n_in,
                              void* d_out, int out_size)
{
    (void)in_sizes; (void)n_in; (void)out_size;
    const float* x      = (const float*)d_in[0];
    const float* f_in_w = (const float*)d_in[1];
    const float* f_cw   = (const float*)d_in[2];
    const float* f_cb   = (const float*)d_in[3];
    const float* f_dtb  = (const float*)d_in[4];
    const float* f_Al   = (const float*)d_in[5];
    const float* f_Dp   = (const float*)d_in[6];
    const float* f_nw   = (const float*)d_in[7];
    const float* f_ow   = (const float*)d_in[8];
    const float* b_in_w = (const float*)d_in[9];
    const float* b_cw   = (const float*)d_in[10];
    const float* b_cb   = (const float*)d_in[11];
    const float* b_dtb  = (const float*)d_in[12];
    const float* b_Al   = (const float*)d_in[13];
    const float* b_Dp   = (const float*)d_in[14];
    const float* b_nw   = (const float*)d_in[15];
    const float* b_ow   = (const float*)d_in[16];
    float* out = (float*)d_out;

    // One-time stream/event setup (first call = correctness run, not captured).
    static cudaStream_t s1 = nullptr;
    static cudaEvent_t e_ip0 = nullptr, e_g1 = nullptr;
    if (!s1) {
        cudaStreamCreateWithFlags(&s1, cudaStreamNonBlocking);
        cudaEventCreateWithFlags(&e_ip0, cudaEventDisableTiming);
        cudaEventCreateWithFlags(&e_g1, cudaEventDisableTiming);
    }

    const int nx  = MROWS * DMODEL / 4;
    const int nwi = DIP * DMODEL / 4;
    const int nwo = DMODEL * DINNER / 4;

    dim3 gIn((DIP + 127) / 128, MROWS / 128);             // 34 x 64
    dim3 gOut(DMODEL / 128, MROWS / 128);                 // 8 x 64
    dim3 gConv((CONVDIM + NHEADS + 255) / 256, MROWS);    // 9 x 8192
    dim3 gScan(NHEADS, BATCH);

    // ---- main stream: dir0 chain ----
    k_round<<<(nx  + 255) / 256, 256>>>(x,      0, nx);   // xr   -> g_xBC[1]
    k_round<<<(nwi + 255) / 256, 256>>>(f_in_w, 1, nwi);  // Win0 -> g_xBC[0]
    k_inproj<<<gIn, 256>>>(0);
    cudaEventRecord(e_ip0, 0);

    // ---- s1: dir1 chain (forked after inproj0; overlaps dir0 tail) ----
    cudaStreamWaitEvent(s1, e_ip0, 0);
    k_round<<<(nwi + 255) / 256, 256, 0, s1>>>(b_in_w, 2, nwi);  // Win1 -> g_y[1]
    k_inproj<<<gIn, 256, 0, s1>>>(1);
    k_conv<<<gConv, 256, 0, s1>>>(b_cw, b_cb, b_dtb, 1);
    k_scan<<<gScan, HEADDIM, 0, s1>>>(b_Al, b_Dp, 1);
    k_gate<<<MROWS, 256, 0, s1>>>(b_nw, 1);
    cudaEventRecord(e_g1, s1);

    // ---- main continues: dir0 tail (overlaps inproj1) ----
    k_conv<<<gConv, 256>>>(f_cw, f_cb, f_dtb, 0);
    k_scan<<<gScan, HEADDIM>>>(f_Al, f_Dp, 0);
    k_gate<<<MROWS, 256>>>(f_nw, 0);
    k_round<<<(nwo + 255) / 256, 256>>>(f_ow, 3, nwo);    // Woutf -> g_xBC[0]
    k_round<<<(nwo + 255) / 256, 256>>>(b_ow, 4, nwo);    // Woutb -> g_xBC[0]+
    k_outproj<<<gOut, 256>>>(out, 0, 0);                  // overlaps dir1 tail

    // ---- join: dir1 out-proj accumulates after gate1 ----
    cudaStreamWaitEvent(0, e_g1, 0);
    k_outproj<<<gOut, 256>>>(out, 1, 1);
}

// round 16
// speedup vs baseline: 1.6664x; 1.6664x over previous
#include <cuda_runtime.h>
#include <cuda_fp16.h>
#include <math.h>
#include <stdint.h>

#define BATCH   4
#define SEQLEN  2048
#define DMODEL  1024
#define DINNER  2048
#define DSTATE  64
#define NHEADS  32
#define HEADDIM 64
#define CONVDIM 2176          // DINNER + 2*DSTATE
#define DIP     4256          // 2*DINNER + 2*DSTATE + NHEADS
#define MROWS   (BATCH*SEQLEN) // 8192
#define DTOFF   4224          // DINNER + CONVDIM

// ---- scratch (static device arrays; same footprint as passing builds) ----
// Alias plan (single stream, R7 ordering):
//   g_y  region : fp16 x (halfs at base)         -> overwritten by scan output floats
//                 after gate: rows hold fp16 y in the first half of each row
//   g_xBC region: fp16 W_in dir0/dir1 (halfs)    -> conv output floats
//                 after scan: fp16 W_out f,b (halfs)
__device__ float g_zx [2][MROWS][DIP];
__device__ float g_xBC[2][MROWS][CONVDIM];
__device__ float g_dt [2][NHEADS][MROWS];   // softplus(dt) TRANSPOSED (h-major)
__device__ float g_y  [2][MROWS][DINNER];

__device__ __forceinline__ int fliprow(int m, int flip) {
    return flip ? ((m & ~(SEQLEN - 1)) | ((SEQLEN - 1) - (m & (SEQLEN - 1)))) : m;
}

// ---- packed f32x2 helpers (Blackwell) ----
typedef unsigned long long ull;
__device__ __forceinline__ ull pack2(float lo, float hi) {
    ull r; asm("mov.b64 %0, {%1, %2};" : "=l"(r) : "f"(lo), "f"(hi)); return r;
}
#define MUL2(d, a, b)    asm("mul.rn.f32x2 %0, %1, %2;" : "=l"(d) : "l"(a), "l"(b))
#define FMA2(d, a, b, c) asm("fma.rn.f32x2 %0, %1, %2, %3;" : "=l"(d) : "l"(a), "l"(b), "l"(c))
#define FMA2ACC(d, a, b) asm("fma.rn.f32x2 %0, %1, %2, %0;" : "+l"(d) : "l"(a), "l"(b))

// ---- cp.async ----
__device__ __forceinline__ void cp_async16(void* smem_dst, const void* gmem_src, int src_bytes) {
    uint32_t s = (uint32_t)__cvta_generic_to_shared(smem_dst);
    asm volatile("cp.async.cg.shared.global [%0], [%1], 16, %2;\n"
                 :: "r"(s), "l"(gmem_src), "r"(src_bytes));
}
__device__ __forceinline__ void cp_commit() { asm volatile("cp.async.commit_group;\n"); }
__device__ __forceinline__ void cp_wait0()  { asm volatile("cp.async.wait_group 0;\n"); }
__device__ __forceinline__ void cp_wait1()  { asm volatile("cp.async.wait_group 1;\n"); }

// fp16 MMA, fp32 accumulate: D(16x8) += A(16x16) * B(16x8)
__device__ __forceinline__ void mma_16n8k16(float c[4], const uint32_t a[4], const uint32_t b[2]) {
    asm volatile("mma.sync.aligned.m16n8k16.row.col.f32.f16.f16.f32 "
                 "{%0,%1,%2,%3}, {%4,%5,%6,%7}, {%8,%9}, {%0,%1,%2,%3};"
                 : "+f"(c[0]), "+f"(c[1]), "+f"(c[2]), "+f"(c[3])
                 : "r"(a[0]), "r"(a[1]), "r"(a[2]), "r"(a[3]), "r"(b[0]), "r"(b[1]));
}

// ============================================================================
// fp32 -> fp16 conversion into aliased scratch regions.
// 0: x -> g_y base   1/2: W_in dir -> g_xBC base (+DIP*DMODEL)
// 3/4: W_out f/b -> g_xBC base (+DMODEL*DINNER)
// ============================================================================
__global__ void __launch_bounds__(256)
k_half(const float* __restrict__ src, int which, int n4)
{
    __half* dst;
    switch (which) {
        case 0:  dst = (__half*)&g_y[0][0][0]; break;
        case 1:  dst = (__half*)&g_xBC[0][0][0]; break;
        case 2:  dst = (__half*)&g_xBC[0][0][0] + (size_t)DIP * DMODEL; break;
        case 3:  dst = (__half*)&g_xBC[0][0][0]; break;
        default: dst = (__half*)&g_xBC[0][0][0] + (size_t)DMODEL * DINNER; break;
    }
    const int i = blockIdx.x * blockDim.x + threadIdx.x;
    if (i < n4) {
        float4 v = ((const float4*)src)[i];
        __half2 h0 = __floats2half2_rn(v.x, v.y);
        __half2 h1 = __floats2half2_rn(v.z, v.w);
        uint2 pk;
        pk.x = *(uint32_t*)&h0;
        pk.y = *(uint32_t*)&h1;
        ((uint2*)dst)[i] = pk;
    }
}

// ============================================================================
// fp16 tensor-core GEMM (m16n8k16, fp32 acc): C[m][n] (+)= sum_k A[m][k]*W[n][k]
// BM=BN=128, BK=32 halfs, 256 thr = 8 warps (2x4), warp tile 64x32.
// 2-stage cp.async, smem pitch 40 halfs (conflict-free: bank=(20g+tig)%32).
// ============================================================================
#define SPH 40   // 32 + 8 pad halfs

template<int N, int K>
__device__ __forceinline__ void hgemm_nt_body(
    const __half* __restrict__ A, int strideA, int flipA,
    const __half* __restrict__ W,
    float* __restrict__ C, int accum)
{
    __shared__ __half As[2][128][SPH];
    __shared__ __half Bs[2][128][SPH];

    const int tid   = threadIdx.x;
    const int mBase = blockIdx.y * 128;
    const int nBase = blockIdx.x * 128;

    // loaders: 512 16B-chunks per matrix per BK=32 chunk; 2 per thread
    // idx = tid + 256*j: r = idx>>2 (0..127), c = idx&3 (16B unit = 8 halfs)
    const __half* ArJ[2]; const __half* WrJ[2];
    uint32_t sOff[2]; int wbJ[2];
    #pragma unroll
    for (int j = 0; j < 2; j++) {
        const int idx = tid + 256 * j;
        const int r = idx >> 2, c = idx & 3;
        ArJ[j] = A + (size_t)fliprow(mBase + r, flipA) * strideA + c * 8;
        const int wn = nBase + r;
        WrJ[j] = W + (size_t)wn * K + c * 8;
        wbJ[j] = (wn < N) ? 16 : 0;
        sOff[j] = r * SPH + c * 8;
    }

    const int lane = tid & 31;
    const int g    = lane >> 2;   // 0..7
    const int tig  = lane & 3;    // 0..3
    const int warp = tid >> 5;
    const int wm   = (warp & 1) * 64;
    const int wnn  = (warp >> 1) * 32;

    float acc[4][4][4];
    #pragma unroll
    for (int mt = 0; mt < 4; mt++)
        #pragma unroll
        for (int nt = 0; nt < 4; nt++)
            #pragma unroll
            for (int c = 0; c < 4; c++) acc[mt][nt][c] = 0.f;

    auto issueChunk = [&](int ch) {
        const int st = ch & 1;
        const int ko = ch * 32;
        #pragma unroll
        for (int j = 0; j < 2; j++) {
            cp_async16(&As[st][0][0] + sOff[j], ArJ[j] + ko, 16);
            cp_async16(&Bs[st][0][0] + sOff[j], WrJ[j] + ko, wbJ[j]);
        }
    };

    issueChunk(0); cp_commit();

    constexpr int NT = K / 32;
    #pragma unroll 1
    for (int kt = 0; kt < NT; kt++) {
        cp_wait0();
        __syncthreads();

        if (kt + 1 < NT) { issueChunk(kt + 1); cp_commit(); }

        const int st = kt & 1;
        #pragma unroll
        for (int ks = 0; ks < 32; ks += 16) {
            uint32_t af[4][4], bf[4][2];
            #pragma unroll
            for (int mt = 0; mt < 4; mt++) {
                const int m0 = wm + mt * 16 + g;
                af[mt][0] = *(const uint32_t*)&As[st][m0][ks + 2 * tig];
                af[mt][1] = *(const uint32_t*)&As[st][m0 + 8][ks + 2 * tig];
                af[mt][2] = *(const uint32_t*)&As[st][m0][ks + 8 + 2 * tig];
                af[mt][3] = *(const uint32_t*)&As[st][m0 + 8][ks + 8 + 2 * tig];
            }
            #pragma unroll
            for (int nt = 0; nt < 4; nt++) {
                const int n0 = wnn + nt * 8 + g;
                bf[nt][0] = *(const uint32_t*)&Bs[st][n0][ks + 2 * tig];
                bf[nt][1] = *(const uint32_t*)&Bs[st][n0][ks + 8 + 2 * tig];
            }
            #pragma unroll
            for (int mt = 0; mt < 4; mt++)
                #pragma unroll
                for (int nt = 0; nt < 4; nt++)
                    mma_16n8k16(acc[mt][nt], af[mt], bf[nt]);
        }
        __syncthreads();
    }

    #pragma unroll
    for (int mt = 0; mt < 4; mt++) {
        const int m0 = mBase + wm + mt * 16 + g;
        float* crow0 = C + (size_t)m0 * N;
        float* crow1 = C + (size_t)(m0 + 8) * N;
        #pragma unroll
        for (int nt = 0; nt < 4; nt++) {
            const int n = nBase + wnn + nt * 8 + tig * 2;
            if (n < N) {
                float2 v0 = make_float2(acc[mt][nt][0], acc[mt][nt][1]);
                float2 v1 = make_float2(acc[mt][nt][2], acc[mt][nt][3]);
                if (accum) {
                    float2 o0 = *(const float2*)(crow0 + n);
                    float2 o1 = *(const float2*)(crow1 + n);
                    v0.x += o0.x; v0.y += o0.y; v1.x += o1.x; v1.y += o1.y;
                }
                *(float2*)(crow0 + n) = v0;
                *(float2*)(crow1 + n) = v1;
            }
        }
    }
}

__global__ void __launch_bounds__(256)
k_inproj()
{
    const int dir = blockIdx.z;
    const __half* xh  = (const __half*)&g_y[0][0][0];
    const __half* win = (const __half*)&g_xBC[0][0][0] + (size_t)dir * DIP * DMODEL;
    hgemm_nt_body<DIP, DMODEL>(xh, DMODEL, dir, win, &g_zx[dir][0][0], 0);
}

__global__ void __launch_bounds__(256)
k_outproj(float* __restrict__ out, int dir, int accum)
{
    // yh lives in the first half of each g_y[dir] row: stride = 2*DINNER halfs
    const __half* yh = (const __half*)&g_y[dir][0][0];
    const __half* wo = (const __half*)&g_xBC[0][0][0] + (size_t)dir * DMODEL * DINNER;
    hgemm_nt_body<DMODEL, DINNER>(yh, 2 * DINNER, dir, wo, out, accum);
}

// ============================================================================
// Depthwise causal conv (width 4) + bias + silu, fused with dt softplus.
// ============================================================================
__global__ void __launch_bounds__(256)
k_conv(const float* __restrict__ f_cw, const float* __restrict__ f_cb,
       const float* __restrict__ f_dtb,
       const float* __restrict__ b_cw, const float* __restrict__ b_cb,
       const float* __restrict__ b_dtb)
{
    const int c   = blockIdx.x * blockDim.x + threadIdx.x;
    const int m   = blockIdx.y;
    const int dir = blockIdx.z;
    const int l   = m & (SEQLEN - 1);

    if (c < CONVDIM) {
        const float* cw = dir ? b_cw : f_cw;
        const float* cb = dir ? b_cb : f_cb;
        float acc = cb[c];
        #pragma unroll
        for (int j = 0; j < 4; j++) {
            const int ls = l - 3 + j;
            if (ls >= 0)
                acc = fmaf(cw[c * 4 + j], g_zx[dir][m - 3 + j][DINNER + c], acc);
        }
        g_xBC[dir][m][c] = acc / (1.f + expf(-acc));
    } else if (c < CONVDIM + NHEADS) {
        const int h = c - CONVDIM;
        const float* dtb = dir ? b_dtb : f_dtb;
        const float v = g_zx[dir][m][DTOFF + h] + dtb[h];
        g_dt[dir][h][m] = (v > 20.f) ? v : log1pf(expf(v));
    }
}

// ============================================================================
// SSD scan v2 (unchanged from R7 passing build)
// ============================================================================
#define SCHUNK 8
__global__ void __launch_bounds__(64)
k_scan(const float* __restrict__ fA, const float* __restrict__ fD,
       const float* __restrict__ bA, const float* __restrict__ bD)
{
    const int h = blockIdx.x, b = blockIdx.y, dir = blockIdx.z;
    const int tid = threadIdx.x;
    const float Ah = -expf((dir ? bA : fA)[h]);
    const float Dh = (dir ? bD : fD)[h];
    const int mBase = b * SEQLEN;

    __shared__ __align__(16) float sX[2][SCHUNK][64];
    __shared__ __align__(16) float sB[2][SCHUNK][64];
    __shared__ __align__(16) float sC[2][SCHUNK][64];
    __shared__ __align__(16) float sDt[2][SCHUNK];

    ull S2[32];
    #pragma unroll
    for (int i = 0; i < 32; i++) S2[i] = 0ull;

    auto issue = [&](int buf, int chunk) {
        #pragma unroll
        for (int j = 0; j < 6; j++) {
            const int idx = tid + 64 * j;
            const int region = idx >> 7;
            const int r = idx & 127;
            const int t = r >> 4;
            const int o = (r & 15) * 4;
            const float* row = &g_xBC[dir][mBase + chunk * SCHUNK + t][0];
            const float* src;
            float* dst;
            if (region == 0)      { src = row + h * HEADDIM + o;     dst = &sX[buf][t][o]; }
            else if (region == 1) { src = row + DINNER + o;          dst = &sB[buf][t][o]; }
            else                  { src = row + DINNER + DSTATE + o; dst = &sC[buf][t][o]; }
            cp_async16(dst, src, 16);
        }
        if (tid < 2)
            cp_async16(&sDt[buf][tid * 4],
                       &g_dt[dir][h][mBase + chunk * SCHUNK + tid * 4], 16);
    };

    constexpr int NC = SEQLEN / SCHUNK;
    issue(0, 0);
    cp_commit();

    #pragma unroll 1
    for (int ch = 0; ch < NC; ch++) {
        const int buf = ch & 1;
        if (ch + 1 < NC) {
            issue(buf ^ 1, ch + 1);
            cp_commit();
            cp_wait1();
        } else {
            cp_wait0();
        }
        __syncthreads();

        #pragma unroll
        for (int t = 0; t < SCHUNK; t++) {
            const float dt = sDt[buf][t];
            const float dA = expf(dt * Ah);
            const float xp = sX[buf][t][tid];
            const float cf = dt * xp;
            const ull dA2 = pack2(dA, dA);
            const ull cf2 = pack2(cf, cf);

            ull y2[4] = {0ull, 0ull, 0ull, 0ull};
            #pragma unroll
            for (int q = 0; q < 16; q++) {
                const ulonglong2 bq = *(const ulonglong2*)&sB[buf][t][q * 4];
                const ulonglong2 cq = *(const ulonglong2*)&sC[buf][t][q * 4];
                ull tmp;
                MUL2(tmp, S2[2*q],   dA2); FMA2(S2[2*q],   cf2, bq.x, tmp);
                FMA2ACC(y2[(2*q)   & 3], S2[2*q],   cq.x);
                MUL2(tmp, S2[2*q+1], dA2); FMA2(S2[2*q+1], cf2, bq.y, tmp);
                FMA2ACC(y2[(2*q+1) & 3], S2[2*q+1], cq.y);
            }
            float ys = 0.f;
            #pragma unroll
            for (int a = 0; a < 4; a++) {
                uint32_t lo, hi;
                asm("mov.b64 {%0, %1}, %2;" : "=r"(lo), "=r"(hi) : "l"(y2[a]));
                ys += __uint_as_float(lo) + __uint_as_float(hi);
            }
            g_y[dir][mBase + ch * SCHUNK + t][h * HEADDIM + tid] = ys + Dh * xp;
        }
        __syncthreads();
    }
}

// ============================================================================
// Gate with silu(z), RMSNorm over DINNER, scale by norm_w.
// Reads g_y floats; writes fp16 y IN PLACE (first half of each row).
// All reads precede the reduction barriers; writes follow them -> safe.
// ============================================================================
__global__ void __launch_bounds__(256)
k_gate(const float* __restrict__ fnw, const float* __restrict__ bnw)
{
    const int m = blockIdx.x, dir = blockIdx.y;
    const int tid = threadIdx.x;
    const float* nw = dir ? bnw : fnw;

    const float4* y4p = (const float4*)&g_y[dir][m][0];
    const float4* z4p = (const float4*)&g_zx[dir][m][0];

    float4 v[2];
    float ss = 0.f;
    #pragma unroll
    for (int i = 0; i < 2; i++) {
        const int idx = tid + i * 256;
        const float4 y4 = y4p[idx];
        const float4 z4 = z4p[idx];
        float4 r;
        r.x = y4.x * (z4.x / (1.f + expf(-z4.x)));
        r.y = y4.y * (z4.y / (1.f + expf(-z4.y)));
        r.z = y4.z * (z4.z / (1.f + expf(-z4.z)));
        r.w = y4.w * (z4.w / (1.f + expf(-z4.w)));
        v[i] = r;
        ss += r.x * r.x + r.y * r.y + r.z * r.z + r.w * r.w;
    }
    __shared__ float red[8];
    #pragma unroll
    for (int o = 16; o > 0; o >>= 1) ss += __shfl_xor_sync(0xffffffffu, ss, o);
    if ((tid & 31) == 0) red[tid >> 5] = ss;
    __syncthreads();
    if (tid < 8) {
        float t = red[tid];
        #pragma unroll
        for (int o = 4; o > 0; o >>= 1) t += __shfl_xor_sync(0xffu, t, o);
        if (tid == 0) red[0] = t;
    }
    __syncthreads();
    const float scale = rsqrtf(red[0] / (float)DINNER + 1e-5f);

    uint2* oh = (uint2*)&g_y[dir][m][0];   // fp16 output, 8B per float4-group
    #pragma unroll
    for (int i = 0; i < 2; i++) {
        const int idx = tid + i * 256;
        const float4 w4 = ((const float4*)nw)[idx];
        float4 r = v[i];
        __half2 h0 = __floats2half2_rn(r.x * scale * w4.x, r.y * scale * w4.y);
        __half2 h1 = __floats2half2_rn(r.z * scale * w4.z, r.w * scale * w4.w);
        uint2 pk;
        pk.x = *(uint32_t*)&h0;
        pk.y = *(uint32_t*)&h1;
        oh[idx] = pk;
    }
}

// ============================================================================
extern "C" void kernel_launch(void* const* d_in, const int* in_sizes, int n_in,
                              void* d_out, int out_size)
{
    (void)in_sizes; (void)n_in; (void)out_size;
    const float* x      = (const float*)d_in[0];
    const float* f_in_w = (const float*)d_in[1];
    const float* f_cw   = (const float*)d_in[2];
    const float* f_cb   = (const float*)d_in[3];
    const float* f_dtb  = (const float*)d_in[4];
    const float* f_Al   = (const float*)d_in[5];
    const float* f_Dp   = (const float*)d_in[6];
    const float* f_nw   = (const float*)d_in[7];
    const float* f_ow   = (const float*)d_in[8];
    const float* b_in_w = (const float*)d_in[9];
    const float* b_cw   = (const float*)d_in[10];
    const float* b_cb   = (const float*)d_in[11];
    const float* b_dtb  = (const float*)d_in[12];
    const float* b_Al   = (const float*)d_in[13];
    const float* b_Dp   = (const float*)d_in[14];
    const float* b_nw   = (const float*)d_in[15];
    const float* b_ow   = (const float*)d_in[16];
    float* out = (float*)d_out;

    const int nx  = MROWS * DMODEL / 4;
    const int nwi = DIP * DMODEL / 4;
    const int nwo = DMODEL * DINNER / 4;

    k_half<<<(nx  + 255) / 256, 256>>>(x,      0, nx);   // xh   -> g_y base
    k_half<<<(nwi + 255) / 256, 256>>>(f_in_w, 1, nwi);  // Win0 -> g_xBC base
    k_half<<<(nwi + 255) / 256, 256>>>(b_in_w, 2, nwi);

    dim3 gIn((DIP + 127) / 128, MROWS / 128, 2);          // 34 x 64 x 2
    k_inproj<<<gIn, 256>>>();

    dim3 gConv((CONVDIM + NHEADS + 255) / 256, MROWS, 2);
    k_conv<<<gConv, 256>>>(f_cw, f_cb, f_dtb, b_cw, b_cb, b_dtb);

    k_scan<<<dim3(NHEADS, BATCH, 2), HEADDIM>>>(f_Al, f_Dp, b_Al, b_Dp);

    // g_xBC fully consumed by k_scan -> reuse for fp16 out-proj weights
    k_half<<<(nwo + 255) / 256, 256>>>(f_ow, 3, nwo);
    k_half<<<(nwo + 255) / 256, 256>>>(b_ow, 4, nwo);

    k_gate<<<dim3(MROWS, 2), 256>>>(f_nw, b_nw);

    dim3 gOut(DMODEL / 128, MROWS / 128);                 // 8 x 64
    k_outproj<<<gOut, 256>>>(out, 0, 0);
    k_outproj<<<gOut, 256>>>(out, 1, 1);
}

// round 17
// speedup vs baseline: 1.7888x; 1.0735x over previous
#include <cuda_runtime.h>
#include <cuda_fp16.h>
#include <math.h>
#include <stdint.h>

#define BATCH   4
#define SEQLEN  2048
#define DMODEL  1024
#define DINNER  2048
#define DSTATE  64
#define NHEADS  32
#define HEADDIM 64
#define CONVDIM 2176          // DINNER + 2*DSTATE
#define DIP     4256          // 2*DINNER + 2*DSTATE + NHEADS
#define MROWS   (BATCH*SEQLEN) // 8192
#define DTOFF   4224          // DINNER + CONVDIM

// ---- scratch (static device arrays; same footprint as passing builds) ----
//   g_y  region : fp16 x (halfs at base) -> scan output floats -> fp16 y in-place
//   g_xBC region: fp16 W_in dir0/1 -> conv activations -> fp16 W_out f,b
__device__ float g_zx [2][MROWS][DIP];
__device__ float g_xBC[2][MROWS][CONVDIM];
__device__ float g_dt [2][NHEADS][MROWS];   // softplus(dt) TRANSPOSED (h-major)
__device__ float g_y  [2][MROWS][DINNER];

__device__ __forceinline__ int fliprow(int m, int flip) {
    return flip ? ((m & ~(SEQLEN - 1)) | ((SEQLEN - 1) - (m & (SEQLEN - 1)))) : m;
}

// ---- packed f32x2 helpers (Blackwell) ----
typedef unsigned long long ull;
__device__ __forceinline__ ull pack2(float lo, float hi) {
    ull r; asm("mov.b64 %0, {%1, %2};" : "=l"(r) : "f"(lo), "f"(hi)); return r;
}
#define MUL2(d, a, b)    asm("mul.rn.f32x2 %0, %1, %2;" : "=l"(d) : "l"(a), "l"(b))
#define FMA2(d, a, b, c) asm("fma.rn.f32x2 %0, %1, %2, %3;" : "=l"(d) : "l"(a), "l"(b), "l"(c))
#define FMA2ACC(d, a, b) asm("fma.rn.f32x2 %0, %1, %2, %0;" : "+l"(d) : "l"(a), "l"(b))

// ---- cp.async ----
__device__ __forceinline__ void cp_async16(void* smem_dst, const void* gmem_src, int src_bytes) {
    uint32_t s = (uint32_t)__cvta_generic_to_shared(smem_dst);
    asm volatile("cp.async.cg.shared.global [%0], [%1], 16, %2;\n"
                 :: "r"(s), "l"(gmem_src), "r"(src_bytes));
}
__device__ __forceinline__ void cp_commit() { asm volatile("cp.async.commit_group;\n"); }
__device__ __forceinline__ void cp_wait0()  { asm volatile("cp.async.wait_group 0;\n"); }
__device__ __forceinline__ void cp_wait1()  { asm volatile("cp.async.wait_group 1;\n"); }

// fp16 MMA, fp32 accumulate
__device__ __forceinline__ void mma_16n8k16(float c[4], const uint32_t a[4],
                                            uint32_t b0, uint32_t b1) {
    asm volatile("mma.sync.aligned.m16n8k16.row.col.f32.f16.f16.f32 "
                 "{%0,%1,%2,%3}, {%4,%5,%6,%7}, {%8,%9}, {%0,%1,%2,%3};"
                 : "+f"(c[0]), "+f"(c[1]), "+f"(c[2]), "+f"(c[3])
                 : "r"(a[0]), "r"(a[1]), "r"(a[2]), "r"(a[3]), "r"(b0), "r"(b1));
}

#define LDSM_X4(r0, r1, r2, r3, addr) \
    asm volatile("ldmatrix.sync.aligned.m8n8.x4.shared.b16 {%0,%1,%2,%3}, [%4];" \
                 : "=r"(r0), "=r"(r1), "=r"(r2), "=r"(r3) : "r"(addr))

// ============================================================================
// fp32 -> fp16 conversion into aliased scratch regions.
// ============================================================================
__global__ void __launch_bounds__(256)
k_half(const float* __restrict__ src, int which, int n4)
{
    __half* dst;
    switch (which) {
        case 0:  dst = (__half*)&g_y[0][0][0]; break;
        case 1:  dst = (__half*)&g_xBC[0][0][0]; break;
        case 2:  dst = (__half*)&g_xBC[0][0][0] + (size_t)DIP * DMODEL; break;
        case 3:  dst = (__half*)&g_xBC[0][0][0]; break;
        default: dst = (__half*)&g_xBC[0][0][0] + (size_t)DMODEL * DINNER; break;
    }
    const int i = blockIdx.x * blockDim.x + threadIdx.x;
    if (i < n4) {
        float4 v = ((const float4*)src)[i];
        __half2 h0 = __floats2half2_rn(v.x, v.y);
        __half2 h1 = __floats2half2_rn(v.z, v.w);
        uint2 pk;
        pk.x = *(uint32_t*)&h0;
        pk.y = *(uint32_t*)&h1;
        ((uint2*)dst)[i] = pk;
    }
}

// ============================================================================
// fp16 GEMM core: BM=BN=128, BK=32 halfs, 8 warps (2x4) of 64x32 tiles,
// 2-stage cp.async, pitch 40 halfs; fragments via ldmatrix.x4 (6 per chunk).
// ============================================================================
#define SPH 40                        // 32 + 8 pad halfs
#define STG_BYTES (128 * SPH * 2)     // 10240 per matrix per stage

__device__ __forceinline__ void ldsm_compute_chunk(
    uint32_t asST, uint32_t bsST, int wm, int wnn, int quad, int rit,
    float acc[4][4][4])
{
    const uint32_t aRow = wm  + (quad & 1) * 8 + rit;
    const uint32_t aCol = (quad >> 1) * 8;
    const uint32_t bRow = wnn + (quad >> 1) * 8 + rit;
    const uint32_t bCol = (quad & 1) * 8;
    #pragma unroll
    for (int ks = 0; ks < 32; ks += 16) {
        uint32_t af[4][4], bq[2][4];
        #pragma unroll
        for (int mt = 0; mt < 4; mt++) {
            const uint32_t addr = asST + ((aRow + mt * 16) * SPH + aCol + ks) * 2;
            LDSM_X4(af[mt][0], af[mt][1], af[mt][2], af[mt][3], addr);
        }
        #pragma unroll
        for (int p = 0; p < 2; p++) {
            const uint32_t addr = bsST + ((bRow + p * 16) * SPH + bCol + ks) * 2;
            LDSM_X4(bq[p][0], bq[p][1], bq[p][2], bq[p][3], addr);
        }
        #pragma unroll
        for (int mt = 0; mt < 4; mt++)
            #pragma unroll
            for (int nt = 0; nt < 4; nt++)
                mma_16n8k16(acc[mt][nt], af[mt],
                            bq[nt >> 1][(nt & 1) * 2],
                            bq[nt >> 1][(nt & 1) * 2 + 1]);
    }
}

template<int N>
__device__ __forceinline__ void gemm_epilogue(
    float acc[4][4][4], float* __restrict__ C,
    int mBase, int nBase, int wm, int wnn, int g, int tig)
{
    #pragma unroll
    for (int mt = 0; mt < 4; mt++) {
        const int m0 = mBase + wm + mt * 16 + g;
        float* crow0 = C + (size_t)m0 * N;
        float* crow1 = C + (size_t)(m0 + 8) * N;
        #pragma unroll
        for (int nt = 0; nt < 4; nt++) {
            const int n = nBase + wnn + nt * 8 + tig * 2;
            if (n < N) {
                *(float2*)(crow0 + n) = make_float2(acc[mt][nt][0], acc[mt][nt][1]);
                *(float2*)(crow1 + n) = make_float2(acc[mt][nt][2], acc[mt][nt][3]);
            }
        }
    }
}

// ---- in-proj: g_zx[dir] = xh @ Win^T (rows flipped for dir=1), K=1024 ----
__global__ void __launch_bounds__(256)
k_inproj()
{
    __shared__ __half As[2][128][SPH];
    __shared__ __half Bs[2][128][SPH];

    const int dir = blockIdx.z;
    const __half* A = (const __half*)&g_y[0][0][0];
    const __half* W = (const __half*)&g_xBC[0][0][0] + (size_t)dir * DIP * DMODEL;
    float* C = &g_zx[dir][0][0];
    constexpr int N = DIP, K = DMODEL;

    const int tid = threadIdx.x;
    const int mBase = blockIdx.y * 128;
    const int nBase = blockIdx.x * 128;

    const __half* ArJ[2]; const __half* WrJ[2];
    uint32_t sOff[2]; int wbJ[2];
    #pragma unroll
    for (int j = 0; j < 2; j++) {
        const int idx = tid + 256 * j;
        const int r = idx >> 2, c = idx & 3;
        ArJ[j] = A + (size_t)fliprow(mBase + r, dir) * K + c * 8;
        const int wn = nBase + r;
        WrJ[j] = W + (size_t)wn * K + c * 8;
        wbJ[j] = (wn < N) ? 16 : 0;
        sOff[j] = r * SPH + c * 8;
    }

    const int lane = tid & 31;
    const int g = lane >> 2, tig = lane & 3;
    const int quad = lane >> 3, rit = lane & 7;
    const int warp = tid >> 5;
    const int wm = (warp & 1) * 64, wnn = (warp >> 1) * 32;

    const uint32_t asBase = (uint32_t)__cvta_generic_to_shared(&As[0][0][0]);
    const uint32_t bsBase = (uint32_t)__cvta_generic_to_shared(&Bs[0][0][0]);

    float acc[4][4][4];
    #pragma unroll
    for (int mt = 0; mt < 4; mt++)
        #pragma unroll
        for (int nt = 0; nt < 4; nt++)
            #pragma unroll
            for (int c = 0; c < 4; c++) acc[mt][nt][c] = 0.f;

    auto issueChunk = [&](int ch) {
        const int st = ch & 1;
        const int ko = ch * 32;
        #pragma unroll
        for (int j = 0; j < 2; j++) {
            cp_async16(&As[st][0][0] + sOff[j], ArJ[j] + ko, 16);
            cp_async16(&Bs[st][0][0] + sOff[j], WrJ[j] + ko, wbJ[j]);
        }
    };

    issueChunk(0); cp_commit();
    constexpr int NT = K / 32;
    #pragma unroll 1
    for (int kt = 0; kt < NT; kt++) {
        cp_wait0();
        __syncthreads();
        if (kt + 1 < NT) { issueChunk(kt + 1); cp_commit(); }
        const int st = kt & 1;
        ldsm_compute_chunk(asBase + st * STG_BYTES, bsBase + st * STG_BYTES,
                           wm, wnn, quad, rit, acc);
        __syncthreads();
    }
    gemm_epilogue<N>(acc, C, mBase, nBase, wm, wnn, g, tig);
}

// ---- fused out-proj: out[m] = y0[m]@W0^T + y1[flip m]@W1^T, K=2*2048 ----
__global__ void __launch_bounds__(256)
k_outproj(float* __restrict__ out)
{
    __shared__ __half As[2][128][SPH];
    __shared__ __half Bs[2][128][SPH];

    constexpr int N = DMODEL, K1 = DINNER;
    const __half* yh0 = (const __half*)&g_y[0][0][0];   // row stride 2*DINNER halfs
    const __half* yh1 = (const __half*)&g_y[1][0][0];
    const __half* wh  = (const __half*)&g_xBC[0][0][0]; // W0 then W1

    const int tid = threadIdx.x;
    const int mBase = blockIdx.y * 128;
    const int nBase = blockIdx.x * 128;

    const __half* Ar0J[2]; const __half* Ar1J[2];
    const __half* W0J[2];  const __half* W1J[2];
    uint32_t sOff[2];
    #pragma unroll
    for (int j = 0; j < 2; j++) {
        const int idx = tid + 256 * j;
        const int r = idx >> 2, c = idx & 3;
        Ar0J[j] = yh0 + (size_t)(mBase + r) * (2 * DINNER) + c * 8;
        Ar1J[j] = yh1 + (size_t)fliprow(mBase + r, 1) * (2 * DINNER) + c * 8;
        const int wn = nBase + r;   // always < 1024
        W0J[j] = wh + (size_t)wn * K1 + c * 8;
        W1J[j] = wh + (size_t)DMODEL * K1 + (size_t)wn * K1 + c * 8;
        sOff[j] = r * SPH + c * 8;
    }

    const int lane = tid & 31;
    const int g = lane >> 2, tig = lane & 3;
    const int quad = lane >> 3, rit = lane & 7;
    const int warp = tid >> 5;
    const int wm = (warp & 1) * 64, wnn = (warp >> 1) * 32;

    const uint32_t asBase = (uint32_t)__cvta_generic_to_shared(&As[0][0][0]);
    const uint32_t bsBase = (uint32_t)__cvta_generic_to_shared(&Bs[0][0][0]);

    float acc[4][4][4];
    #pragma unroll
    for (int mt = 0; mt < 4; mt++)
        #pragma unroll
        for (int nt = 0; nt < 4; nt++)
            #pragma unroll
            for (int c = 0; c < 4; c++) acc[mt][nt][c] = 0.f;

    constexpr int NSEG = K1 / 32;   // 64 chunks per segment
    auto issueChunk = [&](int ch) {
        const int st = ch & 1;
        const int seg = (ch >= NSEG);
        const int ko = (ch - (seg ? NSEG : 0)) * 32;
        #pragma unroll
        for (int j = 0; j < 2; j++) {
            cp_async16(&As[st][0][0] + sOff[j], (seg ? Ar1J[j] : Ar0J[j]) + ko, 16);
            cp_async16(&Bs[st][0][0] + sOff[j], (seg ? W1J[j]  : W0J[j])  + ko, 16);
        }
    };

    issueChunk(0); cp_commit();
    constexpr int NT = 2 * NSEG;   // 128
    #pragma unroll 1
    for (int kt = 0; kt < NT; kt++) {
        cp_wait0();
        __syncthreads();
        if (kt + 1 < NT) { issueChunk(kt + 1); cp_commit(); }
        const int st = kt & 1;
        ldsm_compute_chunk(asBase + st * STG_BYTES, bsBase + st * STG_BYTES,
                           wm, wnn, quad, rit, acc);
        __syncthreads();
    }
    gemm_epilogue<N>(acc, out, mBase, nBase, wm, wnn, g, tig);
}

// ============================================================================
// Depthwise causal conv (width 4) + bias + silu, fused with dt softplus.
// ============================================================================
__global__ void __launch_bounds__(256)
k_conv(const float* __restrict__ f_cw, const float* __restrict__ f_cb,
       const float* __restrict__ f_dtb,
       const float* __restrict__ b_cw, const float* __restrict__ b_cb,
       const float* __restrict__ b_dtb)
{
    const int c   = blockIdx.x * blockDim.x + threadIdx.x;
    const int m   = blockIdx.y;
    const int dir = blockIdx.z;
    const int l   = m & (SEQLEN - 1);

    if (c < CONVDIM) {
        const float* cw = dir ? b_cw : f_cw;
        const float* cb = dir ? b_cb : f_cb;
        float acc = cb[c];
        #pragma unroll
        for (int j = 0; j < 4; j++) {
            const int ls = l - 3 + j;
            if (ls >= 0)
                acc = fmaf(cw[c * 4 + j], g_zx[dir][m - 3 + j][DINNER + c], acc);
        }
        g_xBC[dir][m][c] = acc / (1.f + expf(-acc));
    } else if (c < CONVDIM + NHEADS) {
        const int h = c - CONVDIM;
        const float* dtb = dir ? b_dtb : f_dtb;
        const float v = g_zx[dir][m][DTOFF + h] + dtb[h];
        g_dt[dir][h][m] = (v > 20.f) ? v : log1pf(expf(v));
    }
}

// ============================================================================
// SSD scan v2 (unchanged from passing builds)
// ============================================================================
#define SCHUNK 8
__global__ void __launch_bounds__(64)
k_scan(const float* __restrict__ fA, const float* __restrict__ fD,
       const float* __restrict__ bA, const float* __restrict__ bD)
{
    const int h = blockIdx.x, b = blockIdx.y, dir = blockIdx.z;
    const int tid = threadIdx.x;
    const float Ah = -expf((dir ? bA : fA)[h]);
    const float Dh = (dir ? bD : fD)[h];
    const int mBase = b * SEQLEN;

    __shared__ __align__(16) float sX[2][SCHUNK][64];
    __shared__ __align__(16) float sB[2][SCHUNK][64];
    __shared__ __align__(16) float sC[2][SCHUNK][64];
    __shared__ __align__(16) float sDt[2][SCHUNK];

    ull S2[32];
    #pragma unroll
    for (int i = 0; i < 32; i++) S2[i] = 0ull;

    auto issue = [&](int buf, int chunk) {
        #pragma unroll
        for (int j = 0; j < 6; j++) {
            const int idx = tid + 64 * j;
            const int region = idx >> 7;
            const int r = idx & 127;
            const int t = r >> 4;
            const int o = (r & 15) * 4;
            const float* row = &g_xBC[dir][mBase + chunk * SCHUNK + t][0];
            const float* src;
            float* dst;
            if (region == 0)      { src = row + h * HEADDIM + o;     dst = &sX[buf][t][o]; }
            else if (region == 1) { src = row + DINNER + o;          dst = &sB[buf][t][o]; }
            else                  { src = row + DINNER + DSTATE + o; dst = &sC[buf][t][o]; }
            cp_async16(dst, src, 16);
        }
        if (tid < 2)
            cp_async16(&sDt[buf][tid * 4],
                       &g_dt[dir][h][mBase + chunk * SCHUNK + tid * 4], 16);
    };

    constexpr int NC = SEQLEN / SCHUNK;
    issue(0, 0);
    cp_commit();

    #pragma unroll 1
    for (int ch = 0; ch < NC; ch++) {
        const int buf = ch & 1;
        if (ch + 1 < NC) {
            issue(buf ^ 1, ch + 1);
            cp_commit();
            cp_wait1();
        } else {
            cp_wait0();
        }
        __syncthreads();

        #pragma unroll
        for (int t = 0; t < SCHUNK; t++) {
            const float dt = sDt[buf][t];
            const float dA = expf(dt * Ah);
            const float xp = sX[buf][t][tid];
            const float cf = dt * xp;
            const ull dA2 = pack2(dA, dA);
            const ull cf2 = pack2(cf, cf);

            ull y2[4] = {0ull, 0ull, 0ull, 0ull};
            #pragma unroll
            for (int q = 0; q < 16; q++) {
                const ulonglong2 bq = *(const ulonglong2*)&sB[buf][t][q * 4];
                const ulonglong2 cq = *(const ulonglong2*)&sC[buf][t][q * 4];
                ull tmp;
                MUL2(tmp, S2[2*q],   dA2); FMA2(S2[2*q],   cf2, bq.x, tmp);
                FMA2ACC(y2[(2*q)   & 3], S2[2*q],   cq.x);
                MUL2(tmp, S2[2*q+1], dA2); FMA2(S2[2*q+1], cf2, bq.y, tmp);
                FMA2ACC(y2[(2*q+1) & 3], S2[2*q+1], cq.y);
            }
            float ys = 0.f;
            #pragma unroll
            for (int a = 0; a < 4; a++) {
                uint32_t lo, hi;
                asm("mov.b64 {%0, %1}, %2;" : "=r"(lo), "=r"(hi) : "l"(y2[a]));
                ys += __uint_as_float(lo) + __uint_as_float(hi);
            }
            g_y[dir][mBase + ch * SCHUNK + t][h * HEADDIM + tid] = ys + Dh * xp;
        }
        __syncthreads();
    }
}

// ============================================================================
// Gate with silu(z), RMSNorm, norm_w scale; writes fp16 y IN PLACE.
// ============================================================================
__global__ void __launch_bounds__(256)
k_gate(const float* __restrict__ fnw, const float* __restrict__ bnw)
{
    const int m = blockIdx.x, dir = blockIdx.y;
    const int tid = threadIdx.x;
    const float* nw = dir ? bnw : fnw;

    const float4* y4p = (const float4*)&g_y[dir][m][0];
    const float4* z4p = (const float4*)&g_zx[dir][m][0];

    float4 v[2];
    float ss = 0.f;
    #pragma unroll
    for (int i = 0; i < 2; i++) {
        const int idx = tid + i * 256;
        const float4 y4 = y4p[idx];
        const float4 z4 = z4p[idx];
        float4 r;
        r.x = y4.x * (z4.x / (1.f + expf(-z4.x)));
        r.y = y4.y * (z4.y / (1.f + expf(-z4.y)));
        r.z = y4.z * (z4.z / (1.f + expf(-z4.z)));
        r.w = y4.w * (z4.w / (1.f + expf(-z4.w)));
        v[i] = r;
        ss += r.x * r.x + r.y * r.y + r.z * r.z + r.w * r.w;
    }
    __shared__ float red[8];
    #pragma unroll
    for (int o = 16; o > 0; o >>= 1) ss += __shfl_xor_sync(0xffffffffu, ss, o);
    if ((tid & 31) == 0) red[tid >> 5] = ss;
    __syncthreads();
    if (tid < 8) {
        float t = red[tid];
        #pragma unroll
        for (int o = 4; o > 0; o >>= 1) t += __shfl_xor_sync(0xffu, t, o);
        if (tid == 0) red[0] = t;
    }
    __syncthreads();
    const float scale = rsqrtf(red[0] / (float)DINNER + 1e-5f);

    uint2* oh = (uint2*)&g_y[dir][m][0];
    #pragma unroll
    for (int i = 0; i < 2; i++) {
        const int idx = tid + i * 256;
        const float4 w4 = ((const float4*)nw)[idx];
        float4 r = v[i];
        __half2 h0 = __floats2half2_rn(r.x * scale * w4.x, r.y * scale * w4.y);
        __half2 h1 = __floats2half2_rn(r.z * scale * w4.z, r.w * scale * w4.w);
        uint2 pk;
        pk.x = *(uint32_t*)&h0;
        pk.y = *(uint32_t*)&h1;
        oh[idx] = pk;
    }
}

// ============================================================================
extern "C" void kernel_launch(void* const* d_in, const int* in_sizes, int n_in,
                              void* d_out, int out_size)
{
    (void)in_sizes; (void)n_in; (void)out_size;
    const float* x      = (const float*)d_in[0];
    const float* f_in_w = (const float*)d_in[1];
    const float* f_cw   = (const float*)d_in[2];
    const float* f_cb   = (const float*)d_in[3];
    const float* f_dtb  = (const float*)d_in[4];
    const float* f_Al   = (const float*)d_in[5];
    const float* f_Dp   = (const float*)d_in[6];
    const float* f_nw   = (const float*)d_in[7];
    const float* f_ow   = (const float*)d_in[8];
    const float* b_in_w = (const float*)d_in[9];
    const float* b_cw   = (const float*)d_in[10];
    const float* b_cb   = (const float*)d_in[11];
    const float* b_dtb  = (const float*)d_in[12];
    const float* b_Al   = (const float*)d_in[13];
    const float* b_Dp   = (const float*)d_in[14];
    const float* b_nw   = (const float*)d_in[15];
    const float* b_ow   = (const float*)d_in[16];
    float* out = (float*)d_out;

    const int nx  = MROWS * DMODEL / 4;
    const int nwi = DIP * DMODEL / 4;
    const int nwo = DMODEL * DINNER / 4;

    k_half<<<(nx  + 255) / 256, 256>>>(x,      0, nx);   // xh   -> g_y base
    k_half<<<(nwi + 255) / 256, 256>>>(f_in_w, 1, nwi);  // Win0 -> g_xBC base
    k_half<<<(nwi + 255) / 256, 256>>>(b_in_w, 2, nwi);

    dim3 gIn((DIP + 127) / 128, MROWS / 128, 2);          // 34 x 64 x 2
    k_inproj<<<gIn, 256>>>();

    dim3 gConv((CONVDIM + NHEADS + 255) / 256, MROWS, 2);
    k_conv<<<gConv, 256>>>(f_cw, f_cb, f_dtb, b_cw, b_cb, b_dtb);

    k_scan<<<dim3(NHEADS, BATCH, 2), HEADDIM>>>(f_Al, f_Dp, b_Al, b_Dp);

    // g_xBC fully consumed by k_scan -> reuse for fp16 out-proj weights
    k_half<<<(nwo + 255) / 256, 256>>>(f_ow, 3, nwo);
    k_half<<<(nwo + 255) / 256, 256>>>(b_ow, 4, nwo);

    k_gate<<<dim3(MROWS, 2), 256>>>(f_nw, b_nw);

    dim3 gOut(DMODEL / 128, MROWS / 128);                 // 8 x 64
    k_outproj<<<gOut, 256>>>(out);
}